// round 11
// baseline (speedup 1.0000x reference)
#include <cuda_runtime.h>
#include <math_constants.h>
#include <cstdint>

// ---------------------------------------------------------------------------
// DetectionLoss: 3-level nearest-neighbor matching + CE/L1 loss on GB300.
//
// ROUND 8: phase-1 scan is now FULLY SCALAR IEEE (__fadd_rn/__fmul_rn/
// __fmaf_rn). The round-7 reg_loss error (0.134) matched the signature of
// ~900 "right d2, wrong index" matches: the f32x2-packed scan vs scalar
// recovery bitwise-equality assumption was unsound. Scalar ops are
// deterministic functions of inputs, so the once-per-chunk recovery
// recompute is bit-identical to the scan by construction.
//
// Phase 1: argmin_j d2 = (gx-px)^2+(gy-py)^2 per (level,batch,gt).
//   - one block per (batch, 1024-pred chunk), 128 threads = one per GT
//   - SoA smem staging -> LDS.128 broadcast reads
//   - group-of-8 fminf tree + once-per-chunk exact index recovery
//   - cross-block merge via atomicMin on packed (d2_bits<<32 | idx) keys
// Phase 2: 6144 warps gather matched cls rows (80 classes), CE + L1 + valid.
// Phase 3: single-block deterministic reduction in double, writes 3 floats.
// Inputs resolved BY ELEMENT COUNT (all 8 sizes pairwise distinct).
// ---------------------------------------------------------------------------

#define BATCH   16
#define NGT     128
#define NC      80
#define HW0     25600
#define HW1     6400
#define HW2     1600
#define CHUNK   1024
#define C0      25              // ceil(HW0/CHUNK)
#define C1      7               // ceil(HW1/CHUNK)
#define C2      2               // ceil(HW2/CHUNK)
#define CPB     (C0 + C1 + C2)  // 34 chunk-blocks per batch
#define NMATCH  (3 * BATCH * NGT)  // 6144

__device__ unsigned long long g_key[NMATCH];
__device__ float g_ce[NMATCH];
__device__ float g_l1[NMATCH];
__device__ float g_w[NMATCH];

// Exact scalar d2 — the ONE definition used by both scan and recovery.
__device__ __forceinline__ float d2_exact(float px, float py, float ngx, float ngy) {
    float dx = __fadd_rn(px, ngx);
    float dy = __fadd_rn(py, ngy);
    return __fmaf_rn(dy, dy, __fmul_rn(dx, dx));
}

// ---------------------------------------------------------------------------
__global__ void init_kernel() {
    int i = blockIdx.x * blockDim.x + threadIdx.x;
    if (i < NMATCH) g_key[i] = 0xFFFFFFFFFFFFFFFFULL;
}

// ---------------------------------------------------------------------------
__global__ __launch_bounds__(128) void argmin_kernel(
    const float* __restrict__ r0, const float* __restrict__ r1,
    const float* __restrict__ r2, const float* __restrict__ gt)
{
    __shared__ __align__(16) float xs[CHUNK];
    __shared__ __align__(16) float ys[CHUNK];

    int bid = blockIdx.x;
    int b   = bid / CPB;
    int cid = bid % CPB;

    int lvl, chunk, hw;
    const float* reg;
    if (cid < C0)            { lvl = 0; chunk = cid;            hw = HW0; reg = r0; }
    else if (cid < C0 + C1)  { lvl = 1; chunk = cid - C0;       hw = HW1; reg = r1; }
    else                     { lvl = 2; chunk = cid - C0 - C1;  hw = HW2; reg = r2; }

    int j0 = chunk * CHUNK;

    // ---- one GT per thread: coalesced float4 load of its box (xy used) -----
    int n = threadIdx.x;
    float4 gbox = ((const float4*)gt)[(size_t)b * NGT + n];
    float ngx = -gbox.x, ngy = -gbox.y;  // (px-gx)^2 == (gx-px)^2 exactly

    // ---- stage xy into SoA smem (pad tail with huge coords -> d2 = inf) ----
    const float4* rp = (const float4*)(reg + (size_t)b * hw * 4);
    for (int t = threadIdx.x; t < CHUNK; t += 128) {
        int j = j0 + t;
        float x, y;
        if (j < hw) { float4 v = rp[j]; x = v.x; y = v.y; }
        else        { x = 3.0e30f; y = 3.0e30f; }
        xs[t] = x; ys[t] = y;
    }
    __syncthreads();

    float best  = CUDART_INF_F;
    int   basej = 0;

    const float4* x4 = (const float4*)xs;
    const float4* y4 = (const float4*)ys;

    #pragma unroll 4
    for (int t = 0; t < CHUNK; t += 8) {
        int i = t >> 2;
        float4 xA = x4[i], xB = x4[i + 1];   // xs[t..t+7]
        float4 yA = y4[i], yB = y4[i + 1];   // ys[t..t+7]

        float a0 = d2_exact(xA.x, yA.x, ngx, ngy);
        float a1 = d2_exact(xA.y, yA.y, ngx, ngy);
        float a2 = d2_exact(xA.z, yA.z, ngx, ngy);
        float a3 = d2_exact(xA.w, yA.w, ngx, ngy);
        float a4 = d2_exact(xB.x, yB.x, ngx, ngy);
        float a5 = d2_exact(xB.y, yB.y, ngx, ngy);
        float a6 = d2_exact(xB.z, yB.z, ngx, ngy);
        float a7 = d2_exact(xB.w, yB.w, ngx, ngy);

        float m01 = fminf(a0, a1);
        float m23 = fminf(a2, a3);
        float m45 = fminf(a4, a5);
        float m67 = fminf(a6, a7);
        float m   = fminf(fminf(m01, m23), fminf(m45, m67));

        bool c = m < best;                 // strict < keeps earliest group
        best  = c ? m : best;
        basej = c ? t : basej;
    }

    // ---- index recovery: recompute with the SAME scalar IEEE ops -> the
    // winning lane recompute is bit-identical, so == always hits. Descending
    // scan => lowest offset wins on exact duplicates (argmin tie-break).
    int off = 0;
    #pragma unroll
    for (int o = 7; o >= 0; --o) {
        float dd = d2_exact(xs[basej + o], ys[basej + o], ngx, ngy);
        if (dd == best) off = o;
    }

    int j = j0 + basej + off;
    unsigned long long key =
        ((unsigned long long)__float_as_uint(best) << 32) | (unsigned int)j;
    atomicMin(&g_key[(lvl * BATCH + b) * NGT + n], key);
}

// ---------------------------------------------------------------------------
__global__ __launch_bounds__(256) void gather_kernel(
    const float* __restrict__ c0, const float* __restrict__ c1,
    const float* __restrict__ c2,
    const float* __restrict__ r0, const float* __restrict__ r1,
    const float* __restrict__ r2,
    const float* __restrict__ gt, const int* __restrict__ labels)
{
    int wid  = (blockIdx.x * blockDim.x + threadIdx.x) >> 5;
    int lane = threadIdx.x & 31;
    if (wid >= NMATCH) return;

    int lvl = wid / (BATCH * NGT);
    int rr  = wid % (BATCH * NGT);
    int b   = rr / NGT;
    int n   = rr % NGT;

    const float* cls; const float* reg; int hw;
    if (lvl == 0)      { cls = c0; reg = r0; hw = HW0; }
    else if (lvl == 1) { cls = c1; reg = r1; hw = HW1; }
    else               { cls = c2; reg = r2; hw = HW2; }

    unsigned long long key = g_key[wid];
    float d2 = __uint_as_float((unsigned int)(key >> 32));
    int   j  = (int)(unsigned int)(key & 0xFFFFFFFFULL);

    float w = (__fsqrt_rn(d2) < 2.5f) ? 1.0f : 0.0f;

    const float* row = cls + ((size_t)b * hw + j) * NC;
    float x0 = row[lane];
    float x1 = row[lane + 32];
    bool  has2 = (lane + 64) < NC;
    float x2 = has2 ? row[lane + 64] : -CUDART_INF_F;

    float mx = fmaxf(x0, fmaxf(x1, x2));
    #pragma unroll
    for (int s = 16; s; s >>= 1) mx = fmaxf(mx, __shfl_xor_sync(0xFFFFFFFFu, mx, s));

    float se = expf(x0 - mx) + expf(x1 - mx) + (has2 ? expf(x2 - mx) : 0.0f);
    #pragma unroll
    for (int s = 16; s; s >>= 1) se += __shfl_xor_sync(0xFFFFFFFFu, se, s);

    if (lane == 0) {
        int   lab = labels[b * NGT + n];
        float ce  = (mx + logf(se)) - row[lab];

        const float* pr = reg + ((size_t)b * hw + j) * 4;
        const float* gb = gt + ((size_t)b * NGT + n) * 4;
        float l1 = fabsf(pr[0] - gb[0]) + fabsf(pr[1] - gb[1]) +
                   fabsf(pr[2] - gb[2]) + fabsf(pr[3] - gb[3]);

        g_ce[wid] = ce * w;
        g_l1[wid] = l1 * w;
        g_w[wid]  = w;
    }
}

// ---------------------------------------------------------------------------
__global__ __launch_bounds__(256) void reduce_kernel(float* __restrict__ out) {
    __shared__ double sc[256], sr[256], sw[256];
    double c = 0.0, r = 0.0, w = 0.0;
    for (int i = threadIdx.x; i < NMATCH; i += 256) {
        c += (double)g_ce[i];
        r += (double)g_l1[i];
        w += (double)g_w[i];
    }
    sc[threadIdx.x] = c; sr[threadIdx.x] = r; sw[threadIdx.x] = w;
    __syncthreads();
    for (int s = 128; s > 0; s >>= 1) {
        if (threadIdx.x < s) {
            sc[threadIdx.x] += sc[threadIdx.x + s];
            sr[threadIdx.x] += sr[threadIdx.x + s];
            sw[threadIdx.x] += sw[threadIdx.x + s];
        }
        __syncthreads();
    }
    if (threadIdx.x == 0) {
        double npos  = sw[0];
        double denom = npos > 1.0 ? npos : 1.0;
        out[0] = (float)(sc[0] / denom);
        out[1] = (float)(sr[0] / denom);
        out[2] = (float)npos;
    }
}

// ---------------------------------------------------------------------------
extern "C" void kernel_launch(void* const* d_in, const int* in_sizes, int n_in,
                              void* d_out, int out_size)
{
    // Resolve inputs BY SIZE (all 8 element counts are pairwise distinct).
    const float* c0 = 0; const float* c1 = 0; const float* c2 = 0;
    const float* r0 = 0; const float* r1 = 0; const float* r2 = 0;
    const float* gt = 0; const int* lb = 0;
    for (int i = 0; i < n_in; ++i) {
        long long s = in_sizes[i];
        void* p = d_in[i];
        if      (s == (long long)BATCH * HW0 * NC) c0 = (const float*)p;  // 32,768,000
        else if (s == (long long)BATCH * HW1 * NC) c1 = (const float*)p;  //  8,192,000
        else if (s == (long long)BATCH * HW2 * NC) c2 = (const float*)p;  //  2,048,000
        else if (s == (long long)BATCH * HW0 * 4)  r0 = (const float*)p;  //  1,638,400
        else if (s == (long long)BATCH * HW1 * 4)  r1 = (const float*)p;  //    409,600
        else if (s == (long long)BATCH * HW2 * 4)  r2 = (const float*)p;  //    102,400
        else if (s == (long long)BATCH * NGT * 4)  gt = (const float*)p;  //      8,192
        else if (s == (long long)BATCH * NGT)      lb = (const int*)p;    //      2,048
    }
    float* out = (float*)d_out;

    init_kernel<<<(NMATCH + 255) / 256, 256>>>();
    argmin_kernel<<<BATCH * CPB, 128>>>(r0, r1, r2, gt);
    gather_kernel<<<(NMATCH * 32 + 255) / 256, 256>>>(c0, c1, c2, r0, r1, r2, gt, lb);
    reduce_kernel<<<1, 256>>>(out);
}

// round 12
// speedup vs baseline: 1.3586x; 1.3586x over previous
#include <cuda_runtime.h>
#include <math_constants.h>
#include <cstdint>

// ---------------------------------------------------------------------------
// DetectionLoss on GB300 — round 12.
//
// R11 ncu: reduce_kernel (1 block) was 17.1us of 39.6us total; init_kernel +
// atomicMin merge cost another launch. This round:
//   - 2 kernels total (argmin, gather+fused reduction w/ last-block finish)
//   - argmin writes per-chunk keys NON-atomically to g_part (no init needed);
//     gather warp-shfl-mins the <=25 chunk partials per match
//   - argmin inner loop uses f32x2 packed add/mul/fma (16 packed ops / 8
//     preds); index recovery recomputes with the SAME packed instructions on
//     the same inputs -> bitwise equality by instruction determinism (the
//     r7 failure was packed scan vs scalar recovery, an inter-path bitwise
//     assumption; this has no such assumption)
//   - gather blocks do deterministic tree partial sums (double); the last
//     block (threadfence + atomic counter, self-resetting) folds 768
//     partials and writes the 3 outputs
// ---------------------------------------------------------------------------

#define BATCH   16
#define NGT     128
#define NC      80
#define HW0     25600
#define HW1     6400
#define HW2     1600
#define CHUNK   1024
#define C0      25              // ceil(HW0/CHUNK)
#define C1      7               // ceil(HW1/CHUNK)
#define C2      2               // ceil(HW2/CHUNK)
#define CPB     (C0 + C1 + C2)  // 34 chunk-blocks per batch
#define NMATCH  (3 * BATCH * NGT)   // 6144
#define GBLK    (NMATCH / 8)        // 768 gather blocks (8 warps each)

__device__ unsigned long long g_part[BATCH * CPB * NGT];  // per-chunk best keys
__device__ double g_pce[GBLK];
__device__ double g_pl1[GBLK];
__device__ double g_pw[GBLK];
__device__ unsigned int g_cnt;   // zero-initialized; finisher resets to 0

// ---- f32x2 packed helpers (sm_100+) ---------------------------------------
__device__ __forceinline__ unsigned long long pk2(float lo, float hi) {
    unsigned long long r;
    asm("mov.b64 %0, {%1,%2};" : "=l"(r) : "f"(lo), "f"(hi));
    return r;
}
__device__ __forceinline__ void upk2(unsigned long long v, float& lo, float& hi) {
    asm("mov.b64 {%0,%1}, %2;" : "=f"(lo), "=f"(hi) : "l"(v));
}
__device__ __forceinline__ unsigned long long add2(unsigned long long a, unsigned long long b) {
    unsigned long long d;
    asm("add.rn.f32x2 %0, %1, %2;" : "=l"(d) : "l"(a), "l"(b));
    return d;
}
__device__ __forceinline__ unsigned long long mul2(unsigned long long a, unsigned long long b) {
    unsigned long long d;
    asm("mul.rn.f32x2 %0, %1, %2;" : "=l"(d) : "l"(a), "l"(b));
    return d;
}
__device__ __forceinline__ unsigned long long fma2(unsigned long long a, unsigned long long b,
                                                   unsigned long long c) {
    unsigned long long d;
    asm("fma.rn.f32x2 %0, %1, %2, %3;" : "=l"(d) : "l"(a), "l"(b), "l"(c));
    return d;
}

// One packed d2 pair: (dy^2 + dx^2) per lane, exact fma form per lane.
// Used IDENTICALLY by scan and recovery -> bitwise-equal results.
__device__ __forceinline__ unsigned long long d2pair(
    unsigned long long xpair, unsigned long long ypair,
    unsigned long long ngxx, unsigned long long ngyy)
{
    unsigned long long dx = add2(xpair, ngxx);
    unsigned long long dy = add2(ypair, ngyy);
    return fma2(dy, dy, mul2(dx, dx));
}

// ---------------------------------------------------------------------------
__global__ __launch_bounds__(128) void argmin_kernel(
    const float* __restrict__ r0, const float* __restrict__ r1,
    const float* __restrict__ r2, const float* __restrict__ gt)
{
    __shared__ __align__(16) float xs[CHUNK];
    __shared__ __align__(16) float ys[CHUNK];

    int bid = blockIdx.x;
    int b   = bid / CPB;
    int cid = bid % CPB;

    int chunk, hw;
    const float* reg;
    if (cid < C0)            { chunk = cid;            hw = HW0; reg = r0; }
    else if (cid < C0 + C1)  { chunk = cid - C0;       hw = HW1; reg = r1; }
    else                     { chunk = cid - C0 - C1;  hw = HW2; reg = r2; }

    int j0 = chunk * CHUNK;

    // one GT per thread: coalesced float4 load of its box (xy used)
    int n = threadIdx.x;
    float4 gbox = ((const float4*)gt)[(size_t)b * NGT + n];
    float ngx = -gbox.x, ngy = -gbox.y;   // (px-gx)^2 == (gx-px)^2 exactly
    unsigned long long ngxx = pk2(ngx, ngx);
    unsigned long long ngyy = pk2(ngy, ngy);

    // stage xy into SoA smem (pad tail with huge coords -> d2 = inf)
    const float4* rp = (const float4*)(reg + (size_t)b * hw * 4);
    for (int t = threadIdx.x; t < CHUNK; t += 128) {
        int j = j0 + t;
        float x, y;
        if (j < hw) { float4 v = rp[j]; x = v.x; y = v.y; }
        else        { x = 3.0e30f; y = 3.0e30f; }
        xs[t] = x; ys[t] = y;
    }
    __syncthreads();

    float best  = CUDART_INF_F;
    int   basej = 0;

    const ulonglong2* xv = (const ulonglong2*)xs;
    const ulonglong2* yv = (const ulonglong2*)ys;

    #pragma unroll 4
    for (int t = 0; t < CHUNK; t += 8) {
        int i = t >> 2;
        ulonglong2 xa = xv[i], xb = xv[i + 1];   // packed (x[t],x[t+1]) ...
        ulonglong2 ya = yv[i], yb = yv[i + 1];

        unsigned long long d0 = d2pair(xa.x, ya.x, ngxx, ngyy);
        unsigned long long d1 = d2pair(xa.y, ya.y, ngxx, ngyy);
        unsigned long long d2 = d2pair(xb.x, yb.x, ngxx, ngyy);
        unsigned long long d3 = d2pair(xb.y, yb.y, ngxx, ngyy);

        float a0, a1, a2, a3, a4, a5, a6, a7;
        upk2(d0, a0, a1);
        upk2(d1, a2, a3);
        upk2(d2, a4, a5);
        upk2(d3, a6, a7);

        float m01 = fminf(a0, a1);
        float m23 = fminf(a2, a3);
        float m45 = fminf(a4, a5);
        float m67 = fminf(a6, a7);
        float m   = fminf(fminf(m01, m23), fminf(m45, m67));

        bool c = m < best;                 // strict < keeps earliest group
        best  = c ? m : best;
        basej = c ? t : basej;
    }

    // ---- index recovery: SAME packed instructions on SAME smem inputs ->
    // winning lane's recompute is bit-identical by determinism, == must hit.
    // Descending order (pair 3..0, hi before lo) => lowest offset wins on
    // exact duplicates, matching argmin's lowest-index tie-break.
    int off = 0;
    {
        int i = basej >> 2;
        ulonglong2 xa = xv[i], xb = xv[i + 1];
        ulonglong2 ya = yv[i], yb = yv[i + 1];
        unsigned long long dp[4];
        dp[0] = d2pair(xa.x, ya.x, ngxx, ngyy);
        dp[1] = d2pair(xa.y, ya.y, ngxx, ngyy);
        dp[2] = d2pair(xb.x, yb.x, ngxx, ngyy);
        dp[3] = d2pair(xb.y, yb.y, ngxx, ngyy);
        #pragma unroll
        for (int p = 3; p >= 0; --p) {
            float lo, hi;
            upk2(dp[p], lo, hi);
            if (hi == best) off = 2 * p + 1;
            if (lo == best) off = 2 * p;       // lo checked after hi: lower wins
        }
    }

    int j = j0 + basej + off;
    unsigned long long key =
        ((unsigned long long)__float_as_uint(best) << 32) | (unsigned int)j;
    g_part[(size_t)bid * NGT + n] = key;   // non-atomic: every slot written
}

// ---------------------------------------------------------------------------
__global__ __launch_bounds__(256) void gather_kernel(
    const float* __restrict__ c0, const float* __restrict__ c1,
    const float* __restrict__ c2,
    const float* __restrict__ r0, const float* __restrict__ r1,
    const float* __restrict__ r2,
    const float* __restrict__ gt, const int* __restrict__ labels,
    float* __restrict__ out)
{
    __shared__ float s_ce[8], s_l1[8], s_w[8];
    __shared__ bool  s_last;

    int tid  = threadIdx.x;
    int wid  = (blockIdx.x * blockDim.x + tid) >> 5;   // global match id
    int wloc = tid >> 5;
    int lane = tid & 31;

    int lvl = wid / (BATCH * NGT);
    int rr  = wid % (BATCH * NGT);
    int b   = rr / NGT;
    int n   = rr % NGT;

    const float* cls; const float* reg; int hw, cbase, ccnt;
    if (lvl == 0)      { cls = c0; reg = r0; hw = HW0; cbase = 0;       ccnt = C0; }
    else if (lvl == 1) { cls = c1; reg = r1; hw = HW1; cbase = C0;      ccnt = C1; }
    else               { cls = c2; reg = r2; hw = HW2; cbase = C0 + C1; ccnt = C2; }

    // ---- merge per-chunk partial keys: lane l holds chunk l's key ----------
    unsigned long long key = 0xFFFFFFFFFFFFFFFFULL;
    if (lane < ccnt)
        key = g_part[((size_t)b * CPB + cbase + lane) * NGT + n];
    #pragma unroll
    for (int s = 16; s; s >>= 1) {
        unsigned long long o = __shfl_xor_sync(0xFFFFFFFFu, key, s);
        key = o < key ? o : key;           // min d2, then min j (packed order)
    }

    float d2 = __uint_as_float((unsigned int)(key >> 32));
    int   j  = (int)(unsigned int)(key & 0xFFFFFFFFULL);

    float w = (__fsqrt_rn(d2) < 2.5f) ? 1.0f : 0.0f;

    // ---- CE over 80 classes (warp-cooperative log-softmax) -----------------
    const float* row = cls + ((size_t)b * hw + j) * NC;
    float x0 = row[lane];
    float x1 = row[lane + 32];
    bool  has2 = (lane + 64) < NC;
    float x2 = has2 ? row[lane + 64] : -CUDART_INF_F;

    float mx = fmaxf(x0, fmaxf(x1, x2));
    #pragma unroll
    for (int s = 16; s; s >>= 1) mx = fmaxf(mx, __shfl_xor_sync(0xFFFFFFFFu, mx, s));

    float se = expf(x0 - mx) + expf(x1 - mx) + (has2 ? expf(x2 - mx) : 0.0f);
    #pragma unroll
    for (int s = 16; s; s >>= 1) se += __shfl_xor_sync(0xFFFFFFFFu, se, s);

    if (lane == 0) {
        int   lab = labels[b * NGT + n];
        float ce  = (mx + logf(se)) - row[lab];

        const float* pr = reg + ((size_t)b * hw + j) * 4;
        const float* gb = gt + ((size_t)b * NGT + n) * 4;
        float l1 = fabsf(pr[0] - gb[0]) + fabsf(pr[1] - gb[1]) +
                   fabsf(pr[2] - gb[2]) + fabsf(pr[3] - gb[3]);

        s_ce[wloc] = ce * w;
        s_l1[wloc] = l1 * w;
        s_w[wloc]  = w;
    }
    __syncthreads();

    // ---- deterministic block partial sum (fixed order, double) ------------
    if (tid == 0) {
        double pc = 0.0, pl = 0.0, pw = 0.0;
        #pragma unroll
        for (int i = 0; i < 8; ++i) {
            pc += (double)s_ce[i];
            pl += (double)s_l1[i];
            pw += (double)s_w[i];
        }
        g_pce[blockIdx.x] = pc;
        g_pl1[blockIdx.x] = pl;
        g_pw[blockIdx.x]  = pw;
        __threadfence();
        unsigned int v = atomicAdd(&g_cnt, 1u);
        s_last = (v == (unsigned int)(gridDim.x - 1));
    }
    __syncthreads();

    // ---- last block folds the 768 partials (fixed order => deterministic) --
    if (s_last) {
        __threadfence();
        __shared__ double rc[256], rl[256], rw[256];
        double pc = 0.0, pl = 0.0, pw = 0.0;
        for (int i = tid; i < GBLK; i += 256) {
            pc += g_pce[i];
            pl += g_pl1[i];
            pw += g_pw[i];
        }
        rc[tid] = pc; rl[tid] = pl; rw[tid] = pw;
        __syncthreads();
        for (int s = 128; s > 0; s >>= 1) {
            if (tid < s) {
                rc[tid] += rc[tid + s];
                rl[tid] += rl[tid + s];
                rw[tid] += rw[tid + s];
            }
            __syncthreads();
        }
        if (tid == 0) {
            double npos  = rw[0];
            double denom = npos > 1.0 ? npos : 1.0;
            out[0] = (float)(rc[0] / denom);
            out[1] = (float)(rl[0] / denom);
            out[2] = (float)npos;
            g_cnt  = 0;                    // self-reset for next graph replay
        }
    }
}

// ---------------------------------------------------------------------------
extern "C" void kernel_launch(void* const* d_in, const int* in_sizes, int n_in,
                              void* d_out, int out_size)
{
    // Resolve inputs BY SIZE (all 8 element counts are pairwise distinct).
    const float* c0 = 0; const float* c1 = 0; const float* c2 = 0;
    const float* r0 = 0; const float* r1 = 0; const float* r2 = 0;
    const float* gt = 0; const int* lb = 0;
    for (int i = 0; i < n_in; ++i) {
        long long s = in_sizes[i];
        void* p = d_in[i];
        if      (s == (long long)BATCH * HW0 * NC) c0 = (const float*)p;  // 32,768,000
        else if (s == (long long)BATCH * HW1 * NC) c1 = (const float*)p;  //  8,192,000
        else if (s == (long long)BATCH * HW2 * NC) c2 = (const float*)p;  //  2,048,000
        else if (s == (long long)BATCH * HW0 * 4)  r0 = (const float*)p;  //  1,638,400
        else if (s == (long long)BATCH * HW1 * 4)  r1 = (const float*)p;  //    409,600
        else if (s == (long long)BATCH * HW2 * 4)  r2 = (const float*)p;  //    102,400
        else if (s == (long long)BATCH * NGT * 4)  gt = (const float*)p;  //      8,192
        else if (s == (long long)BATCH * NGT)      lb = (const int*)p;    //      2,048
    }
    float* out = (float*)d_out;

    argmin_kernel<<<BATCH * CPB, 128>>>(r0, r1, r2, gt);
    gather_kernel<<<GBLK, 256>>>(c0, c1, c2, r0, r1, r2, gt, lb, out);
}